// round 7
// baseline (speedup 1.0000x reference)
#include <cuda_runtime.h>

// Shapes (fixed by the problem): inputs [L,B,C,H,W] fp32, W [C,C] fp32
#define DL 4
#define DB 8
#define DC 256
#define DHW 4096             // 64*64
#define LBC (DL*DB*DC)       // 8192
#define VEC_PER_LBC 1024     // float4 per (l,b,c) row
#define BPB 512              // blocks per batch (2 rows each; 1024 rows/batch)
#define TOTAL_BLOCKS (DB * BPB)   // 4096

__device__ float g_gap[LBC];
__device__ int   g_done[DB];   // arrival count (rows published)
__device__ int   g_fin[DB];    // finish count (for self-reset)

// ---------------------------------------------------------------------------
// One block per two consecutive rows (l,b,c),(l,b,c+1). Holds the 32KB of
// data in registers across the per-batch sync, so the input is read ONCE.
// ---------------------------------------------------------------------------
__global__ void __launch_bounds__(256, 4)
fused_kernel(const float* __restrict__ in, const float* __restrict__ Wm,
             float* __restrict__ out) {
    const int bid = blockIdx.x;
    const int b   = bid >> 9;              // batch (blocks batch-contiguous)
    const int j   = bid & (BPB - 1);
    const int l0  = j >> 7;                // level
    const int c   = (j & 127) * 2;         // first of two channels
    const int g0  = (l0 * DB + b) * DC + c;
    const int t   = threadIdx.x;

    const float4* base = reinterpret_cast<const float4*>(in) + (size_t)g0 * VEC_PER_LBC;

    // ---- 1) front-batch ALL data loads (32KB contiguous, MLP=8) ----
    float4 v[8];
#pragma unroll
    for (int i = 0; i < 8; ++i) v[i] = base[i * 256 + t];

    // W rows for this block's two output channels (independent, issue early)
    const float wv0 = __ldg(&Wm[(c + 0) * DC + t]);
    const float wv1 = __ldg(&Wm[(c + 1) * DC + t]);

    // ---- 2) reduce both rows to means, publish ----
    float s0 = 0.f, s1 = 0.f;
#pragma unroll
    for (int i = 0; i < 4; ++i) s0 += (v[i].x + v[i].y) + (v[i].z + v[i].w);
#pragma unroll
    for (int i = 4; i < 8; ++i) s1 += (v[i].x + v[i].y) + (v[i].z + v[i].w);

#pragma unroll
    for (int o = 16; o > 0; o >>= 1) {
        s0 += __shfl_xor_sync(0xffffffffu, s0, o);
        s1 += __shfl_xor_sync(0xffffffffu, s1, o);
    }

    __shared__ float ws[8][2];
    if ((t & 31) == 0) { ws[t >> 5][0] = s0; ws[t >> 5][1] = s1; }
    __syncthreads();
    if (t == 0) {
        float a = 0.f, bb = 0.f;
#pragma unroll
        for (int w = 0; w < 8; ++w) { a += ws[w][0]; bb += ws[w][1]; }
        g_gap[g0 + 0] = a  * (1.0f / (float)DHW);
        g_gap[g0 + 1] = bb * (1.0f / (float)DHW);
        __threadfence();                   // release
        atomicAdd(&g_done[b], 1);
    }

    // ---- 3) wait for all rows of this batch (spin AFTER our memory work) ----
    if (t == 0) {
        while (*((volatile int*)&g_done[b]) < BPB) __nanosleep(64);
        __threadfence();                   // acquire
    }
    __syncthreads();

    // ---- 4) attention scores for d=c and d=c+1; thread t owns channel t ----
    float gp[DL];
#pragma unroll
    for (int l = 0; l < DL; ++l) gp[l] = __ldcg(&g_gap[(l * DB + b) * DC + t]);

    float p0[DL], p1[DL];
#pragma unroll
    for (int l = 0; l < DL; ++l) { p0[l] = wv0 * gp[l]; p1[l] = wv1 * gp[l]; }

#pragma unroll
    for (int o = 16; o > 0; o >>= 1)
#pragma unroll
        for (int l = 0; l < DL; ++l) {
            p0[l] += __shfl_xor_sync(0xffffffffu, p0[l], o);
            p1[l] += __shfl_xor_sync(0xffffffffu, p1[l], o);
        }

    __shared__ float sred[8][2][DL];
    if ((t & 31) == 0) {
#pragma unroll
        for (int l = 0; l < DL; ++l) {
            sred[t >> 5][0][l] = p0[l];
            sred[t >> 5][1][l] = p1[l];
        }
    }
    __syncthreads();

    float sc0[DL], sc1[DL];
#pragma unroll
    for (int l = 0; l < DL; ++l) {
        float a = 0.f, bb = 0.f;
#pragma unroll
        for (int w = 0; w < 8; ++w) { a += sred[w][0][l]; bb += sred[w][1][l]; }
        sc0[l] = a; sc1[l] = bb;
    }

    // softmax over L for each of the two channels; select level l0
    float m0 = sc0[0], m1 = sc1[0];
#pragma unroll
    for (int l = 1; l < DL; ++l) { m0 = fmaxf(m0, sc0[l]); m1 = fmaxf(m1, sc1[l]); }
    float sum0 = 0.f, sum1 = 0.f, e00 = 0.f, e11 = 0.f;
#pragma unroll
    for (int l = 0; l < DL; ++l) {
        float e0 = __expf(sc0[l] - m0);
        float e1 = __expf(sc1[l] - m1);
        sum0 += e0; sum1 += e1;
        if (l == l0) { e00 = e0; e11 = e1; }
    }
    const float a0 = e00 / sum0;
    const float a1 = e11 / sum1;

    // ---- 5) multiply register-held data, stream out ----
    float4* q = reinterpret_cast<float4*>(out) + (size_t)g0 * VEC_PER_LBC;
#pragma unroll
    for (int i = 0; i < 4; ++i) {
        v[i].x *= a0; v[i].y *= a0; v[i].z *= a0; v[i].w *= a0;
        __stcs(&q[i * 256 + t], v[i]);
    }
#pragma unroll
    for (int i = 4; i < 8; ++i) {
        v[i].x *= a1; v[i].y *= a1; v[i].z *= a1; v[i].w *= a1;
        __stcs(&q[i * 256 + t], v[i]);
    }

    // ---- 6) self-reset counters for the next graph replay ----
    __syncthreads();
    if (t == 0) {
        const int f = atomicAdd(&g_fin[b], 1);
        if (f == BPB - 1) { g_done[b] = 0; g_fin[b] = 0; __threadfence(); }
    }
}

// ---------------------------------------------------------------------------
extern "C" void kernel_launch(void* const* d_in, const int* in_sizes, int n_in,
                              void* d_out, int out_size) {
    const float* in = (const float*)d_in[0];   // [L,B,C,H,W]
    const float* Wm = (const float*)d_in[1];   // [C,C]
    float* out = (float*)d_out;

    fused_kernel<<<TOTAL_BLOCKS, 256>>>(in, Wm, out);
}

// round 8
// speedup vs baseline: 1.2117x; 1.2117x over previous
#include <cuda_runtime.h>

// Shapes (fixed by the problem): inputs [L,B,C,H,W] fp32, W [C,C] fp32
#define DL 4
#define DB 8
#define DC 256
#define DHW 4096            // 64*64
#define LBC (DL*DB*DC)      // 8192
#define VEC_PER_LBC 1024    // float4 per (l,b,c) row

__device__ float g_gap[LBC];

// ---------------------------------------------------------------------------
// Kernel 1: global average pool. One block per TWO rows (32KB contiguous),
// 8 front-batched float4 loads (MLP=8). Default cache policy: fills L2
// (evict-normal) so the mul pass re-reads as hits.
// ---------------------------------------------------------------------------
__global__ void __launch_bounds__(256) gap_kernel(const float* __restrict__ in) {
    const int pair = blockIdx.x;                       // 0..4095
    const float4* p = reinterpret_cast<const float4*>(in) + (size_t)pair * (2 * VEC_PER_LBC);
    const int t = threadIdx.x;

    float4 v[8];
#pragma unroll
    for (int i = 0; i < 8; ++i) v[i] = p[i * 256 + t]; // front-batched, coalesced

    float s0 = 0.f, s1 = 0.f;
#pragma unroll
    for (int i = 0; i < 4; ++i) s0 += (v[i].x + v[i].y) + (v[i].z + v[i].w);
#pragma unroll
    for (int i = 4; i < 8; ++i) s1 += (v[i].x + v[i].y) + (v[i].z + v[i].w);

#pragma unroll
    for (int o = 16; o > 0; o >>= 1) {
        s0 += __shfl_xor_sync(0xffffffffu, s0, o);
        s1 += __shfl_xor_sync(0xffffffffu, s1, o);
    }

    __shared__ float ws[8][2];
    if ((t & 31) == 0) { ws[t >> 5][0] = s0; ws[t >> 5][1] = s1; }
    __syncthreads();
    if (t == 0) {
        float a = 0.f, b = 0.f;
#pragma unroll
        for (int w = 0; w < 8; ++w) { a += ws[w][0]; b += ws[w][1]; }
        g_gap[2 * pair + 0] = a * (1.0f / (float)DHW);
        g_gap[2 * pair + 1] = b * (1.0f / (float)DHW);
    }
}

// ---------------------------------------------------------------------------
// Kernel 2 (fused): attention + multiply. One block per (l,b,c), REVERSE
// traversal (tail of input is L2-hot from gap). Reads: __ldcs (evict-first,
// consumed once). Stores: __stwt (write-through, NO L2 allocation) so the
// output stream cannot evict the still-needed input window.
// ---------------------------------------------------------------------------
__global__ void __launch_bounds__(256) fused_mul_kernel(const float* __restrict__ in,
                                                         const float* __restrict__ Wm,
                                                         float* __restrict__ out) {
    const int rb = (int)gridDim.x - 1 - (int)blockIdx.x;   // reverse traversal
    const int l0 = rb >> 11;            // rb / (DB*DC)
    const int b  = (rb >> 8) & (DB - 1);
    const int d  = rb & (DC - 1);
    const int t  = threadIdx.x;

    const size_t base = (size_t)rb * VEC_PER_LBC;
    const float4* p = reinterpret_cast<const float4*>(in) + base;
    float4* q = reinterpret_cast<float4*>(out) + base;

    // 1) front-batch the big loads (MLP=4) — attn math hides under them
    float4 v[4];
#pragma unroll
    for (int i = 0; i < 4; ++i) v[i] = __ldcs(&p[i * 256 + t]);

    // 2) attention scores: thread t owns input-channel c=t
    const float wv = __ldg(&Wm[d * DC + t]);
    float part[DL];
#pragma unroll
    for (int l = 0; l < DL; ++l) part[l] = wv * g_gap[(l * DB + b) * DC + t];

#pragma unroll
    for (int o = 16; o > 0; o >>= 1)
#pragma unroll
        for (int l = 0; l < DL; ++l) part[l] += __shfl_xor_sync(0xffffffffu, part[l], o);

    __shared__ float sred[8][DL];
    if ((t & 31) == 0) {
#pragma unroll
        for (int l = 0; l < DL; ++l) sred[t >> 5][l] = part[l];
    }
    __syncthreads();

    float sc[DL];
#pragma unroll
    for (int l = 0; l < DL; ++l) {
        float s = 0.f;
#pragma unroll
        for (int w = 0; w < 8; ++w) s += sred[w][l];   // smem broadcast, conflict-free
        sc[l] = s;
    }

    // 3) softmax over L, select this block's level
    float m = sc[0];
#pragma unroll
    for (int l = 1; l < DL; ++l) m = fmaxf(m, sc[l]);
    float sum = 0.f, el0 = 0.f;
#pragma unroll
    for (int l = 0; l < DL; ++l) {
        float e = __expf(sc[l] - m);
        sum += e;
        if (l == l0) el0 = e;
    }
    const float a = el0 / sum;

    // 4) multiply + write-through stores (no L2 allocation)
#pragma unroll
    for (int i = 0; i < 4; ++i) {
        v[i].x *= a; v[i].y *= a; v[i].z *= a; v[i].w *= a;
        __stwt(&q[i * 256 + t], v[i]);
    }
}

// ---------------------------------------------------------------------------
extern "C" void kernel_launch(void* const* d_in, const int* in_sizes, int n_in,
                              void* d_out, int out_size) {
    const float* in = (const float*)d_in[0];   // [L,B,C,H,W]
    const float* Wm = (const float*)d_in[1];   // [C,C]
    float* out = (float*)d_out;

    gap_kernel<<<LBC / 2, 256>>>(in);
    fused_mul_kernel<<<LBC, 256>>>(in, Wm, out);
}

// round 10
// speedup vs baseline: 1.3004x; 1.0732x over previous
#include <cuda_runtime.h>

// Shapes (fixed by the problem): inputs [L,B,C,H,W] fp32, W [C,C] fp32
#define DL 4
#define DB 8
#define DC 256
#define DHW 4096            // 64*64
#define LBC (DL*DB*DC)      // 8192
#define VEC_PER_LBC 1024    // float4 per (l,b,c) row

__device__ float g_gap[LBC];

// ---------------------------------------------------------------------------
// Kernel 1: global average pool. One block per TWO rows (32KB contiguous),
// 8 front-batched float4 loads (MLP=8). Triggers the dependent mul launch as
// soon as its loads are issued so mul's CTAs ramp while gap drains.
// ---------------------------------------------------------------------------
__global__ void __launch_bounds__(256) gap_kernel(const float* __restrict__ in) {
    const int pair = blockIdx.x;                       // 0..4095
    const float4* p = reinterpret_cast<const float4*>(in) + (size_t)pair * (2 * VEC_PER_LBC);
    const int t = threadIdx.x;

    float4 v[8];
#pragma unroll
    for (int i = 0; i < 8; ++i) v[i] = p[i * 256 + t]; // front-batched, coalesced

    // Allow the dependent fused_mul launch to start ramping now.
    cudaTriggerProgrammaticLaunchCompletion();

    float s0 = 0.f, s1 = 0.f;
#pragma unroll
    for (int i = 0; i < 4; ++i) s0 += (v[i].x + v[i].y) + (v[i].z + v[i].w);
#pragma unroll
    for (int i = 4; i < 8; ++i) s1 += (v[i].x + v[i].y) + (v[i].z + v[i].w);

#pragma unroll
    for (int o = 16; o > 0; o >>= 1) {
        s0 += __shfl_xor_sync(0xffffffffu, s0, o);
        s1 += __shfl_xor_sync(0xffffffffu, s1, o);
    }

    __shared__ float ws[8][2];
    if ((t & 31) == 0) { ws[t >> 5][0] = s0; ws[t >> 5][1] = s1; }
    __syncthreads();
    if (t == 0) {
        float a = 0.f, b = 0.f;
#pragma unroll
        for (int w = 0; w < 8; ++w) { a += ws[w][0]; b += ws[w][1]; }
        g_gap[2 * pair + 0] = a * (1.0f / (float)DHW);
        g_gap[2 * pair + 1] = b * (1.0f / (float)DHW);
    }
}

// ---------------------------------------------------------------------------
// Kernel 2 (fused, PDL secondary): attention + multiply. One block per
// (l,b,c), REVERSE traversal (tail of input is L2-hot from gap). Input reads
// and W row are prefetched BEFORE the grid dependency sync (they don't depend
// on gap); the gap-dependent attn math runs after the sync.
// ---------------------------------------------------------------------------
__global__ void __launch_bounds__(256) fused_mul_kernel(const float* __restrict__ in,
                                                         const float* __restrict__ Wm,
                                                         float* __restrict__ out) {
    const int rb = (int)gridDim.x - 1 - (int)blockIdx.x;   // reverse traversal
    const int l0 = rb >> 11;            // rb / (DB*DC)
    const int b  = (rb >> 8) & (DB - 1);
    const int d  = rb & (DC - 1);
    const int t  = threadIdx.x;

    const size_t base = (size_t)rb * VEC_PER_LBC;
    const float4* p = reinterpret_cast<const float4*>(in) + base;
    float4* q = reinterpret_cast<float4*>(out) + base;

    // 1) prefetch big loads (independent of gap) — overlap primary's tail
    float4 v[4];
#pragma unroll
    for (int i = 0; i < 4; ++i) v[i] = __ldcs(&p[i * 256 + t]);
    const float wv = __ldg(&Wm[d * DC + t]);

    // 2) wait for gap grid completion (g_gap now visible)
    cudaGridDependencySynchronize();

    // 3) attention scores: thread t owns input-channel c=t
    float part[DL];
#pragma unroll
    for (int l = 0; l < DL; ++l) part[l] = wv * g_gap[(l * DB + b) * DC + t];

#pragma unroll
    for (int o = 16; o > 0; o >>= 1)
#pragma unroll
        for (int l = 0; l < DL; ++l) part[l] += __shfl_xor_sync(0xffffffffu, part[l], o);

    __shared__ float sred[8][DL];
    if ((t & 31) == 0) {
#pragma unroll
        for (int l = 0; l < DL; ++l) sred[t >> 5][l] = part[l];
    }
    __syncthreads();

    float sc[DL];
#pragma unroll
    for (int l = 0; l < DL; ++l) {
        float s = 0.f;
#pragma unroll
        for (int w = 0; w < 8; ++w) s += sred[w][l];   // smem broadcast, conflict-free
        sc[l] = s;
    }

    // 4) softmax over L, select this block's level
    float m = sc[0];
#pragma unroll
    for (int l = 1; l < DL; ++l) m = fmaxf(m, sc[l]);
    float sum = 0.f, el0 = 0.f;
#pragma unroll
    for (int l = 0; l < DL; ++l) {
        float e = __expf(sc[l] - m);
        sum += e;
        if (l == l0) el0 = e;
    }
    const float a = el0 / sum;

    // 5) multiply + evict-first stores
#pragma unroll
    for (int i = 0; i < 4; ++i) {
        v[i].x *= a; v[i].y *= a; v[i].z *= a; v[i].w *= a;
        __stcs(&q[i * 256 + t], v[i]);
    }
}

// ---------------------------------------------------------------------------
extern "C" void kernel_launch(void* const* d_in, const int* in_sizes, int n_in,
                              void* d_out, int out_size) {
    const float* in = (const float*)d_in[0];   // [L,B,C,H,W]
    const float* Wm = (const float*)d_in[1];   // [C,C]
    float* out = (float*)d_out;

    gap_kernel<<<LBC / 2, 256>>>(in);

    // Secondary launch with programmatic stream serialization (PDL).
    cudaLaunchConfig_t cfg = {};
    cfg.gridDim = dim3(LBC);
    cfg.blockDim = dim3(256);
    cfg.dynamicSmemBytes = 0;
    cfg.stream = 0;
    cudaLaunchAttribute attr[1];
    attr[0].id = cudaLaunchAttributeProgrammaticStreamSerialization;
    attr[0].val.programmaticStreamSerializationAllowed = 1;
    cfg.attrs = attr;
    cfg.numAttrs = 1;
    cudaLaunchKernelEx(&cfg, fused_mul_kernel, in, Wm, out);
}

// round 12
// speedup vs baseline: 1.3317x; 1.0241x over previous
#include <cuda_runtime.h>

// Shapes (fixed by the problem): inputs [L,B,C,H,W] fp32, W [C,C] fp32
#define DL 4
#define DB 8
#define DC 256
#define DHW 4096             // 64*64
#define LBC (DL*DB*DC)       // 8192
#define VEC_PER_LBC 1024     // float4 per (l,b,c) row
#define CHB 4                // batches per chunk (67 MB, fits L2)
#define CH_ROWS (DL*CHB*DC)  // 4096 rows per chunk
#define G_BLOCKS (CH_ROWS/2) // 2048 (2 rows per G block)
#define M_BLOCKS (CH_ROWS)   // 4096 (1 row per M block)

__device__ float g_gap[LBC];

// ---------------------------------------------------------------------------
// G(b0): average-pool chunk [b0, b0+CHB). One block per two consecutive rows
// (32KB contiguous, MLP=8). Evict-normal fills: lines must survive until M.
// Triggers the dependent launch as soon as its loads are issued.
// ---------------------------------------------------------------------------
__global__ void __launch_bounds__(256) g_kernel(const float* __restrict__ in, int b0) {
    const int j  = blockIdx.x;               // 0..G_BLOCKS-1
    const int w0 = 2 * j;                    // first chunk-row
    const int l  = w0 >> 10;                 // 4 levels x 1024 rows
    const int bi = (w0 >> 8) & (CHB - 1);
    const int c  = w0 & 255;                 // even channel
    const int g0 = (l * DB + b0 + bi) * DC + c;

    const float4* base = reinterpret_cast<const float4*>(in) + (size_t)g0 * VEC_PER_LBC;
    const int t = threadIdx.x;

    float4 v[8];
#pragma unroll
    for (int i = 0; i < 8; ++i) v[i] = base[i * 256 + t];

    cudaTriggerProgrammaticLaunchCompletion();   // let the next kernel ramp

    float s0 = 0.f, s1 = 0.f;
#pragma unroll
    for (int i = 0; i < 4; ++i) s0 += (v[i].x + v[i].y) + (v[i].z + v[i].w);
#pragma unroll
    for (int i = 4; i < 8; ++i) s1 += (v[i].x + v[i].y) + (v[i].z + v[i].w);

#pragma unroll
    for (int o = 16; o > 0; o >>= 1) {
        s0 += __shfl_xor_sync(0xffffffffu, s0, o);
        s1 += __shfl_xor_sync(0xffffffffu, s1, o);
    }

    __shared__ float ws[8][2];
    if ((t & 31) == 0) { ws[t >> 5][0] = s0; ws[t >> 5][1] = s1; }
    __syncthreads();
    if (t == 0) {
        float a = 0.f, b = 0.f;
#pragma unroll
        for (int w = 0; w < 8; ++w) { a += ws[w][0]; b += ws[w][1]; }
        g_gap[g0 + 0] = a * (1.0f / (float)DHW);
        g_gap[g0 + 1] = b * (1.0f / (float)DHW);
    }
}

// ---------------------------------------------------------------------------
// M(b0): fused attention + multiply for chunk [b0, b0+CHB). One block per
// row. Prefetch input reads (__ldcs, L2-hot from G) and the W row BEFORE the
// grid-dependency sync; after the sync compute the 4 scores, softmax over L,
// multiply, stream out (__stcs evict-first: protect the next chunk's fills).
// ---------------------------------------------------------------------------
__global__ void __launch_bounds__(256) m_kernel(const float* __restrict__ in,
                                                const float* __restrict__ Wm,
                                                float* __restrict__ out, int b0) {
    const int w  = blockIdx.x;               // 0..M_BLOCKS-1
    const int l0 = w >> 10;
    const int bi = (w >> 8) & (CHB - 1);
    const int d  = w & 255;
    const int b  = b0 + bi;
    const int g  = (l0 * DB + b) * DC + d;
    const int t  = threadIdx.x;

    const size_t base = (size_t)g * VEC_PER_LBC;
    const float4* p = reinterpret_cast<const float4*>(in) + base;
    float4* q = reinterpret_cast<float4*>(out) + base;

    // 1) prefetch (independent of g_gap) — overlaps G's tail via PDL
    float4 v[4];
#pragma unroll
    for (int i = 0; i < 4; ++i) v[i] = __ldcs(&p[i * 256 + t]);
    const float wv = __ldg(&Wm[d * DC + t]);

    cudaTriggerProgrammaticLaunchCompletion();   // let the next G ramp

    // 2) wait for our G's grid completion (g_gap for this chunk visible)
    cudaGridDependencySynchronize();

    // 3) attention scores: thread t owns input-channel c=t
    float part[DL];
#pragma unroll
    for (int l = 0; l < DL; ++l) part[l] = wv * g_gap[(l * DB + b) * DC + t];

#pragma unroll
    for (int o = 16; o > 0; o >>= 1)
#pragma unroll
        for (int l = 0; l < DL; ++l) part[l] += __shfl_xor_sync(0xffffffffu, part[l], o);

    __shared__ float sred[8][DL];
    if ((t & 31) == 0) {
#pragma unroll
        for (int l = 0; l < DL; ++l) sred[t >> 5][l] = part[l];
    }
    __syncthreads();

    float sc[DL];
#pragma unroll
    for (int l = 0; l < DL; ++l) {
        float s = 0.f;
#pragma unroll
        for (int w8 = 0; w8 < 8; ++w8) s += sred[w8][l];
        sc[l] = s;
    }

    // 4) softmax over L, select this block's level
    float m = sc[0];
#pragma unroll
    for (int l = 1; l < DL; ++l) m = fmaxf(m, sc[l]);
    float sum = 0.f, el0 = 0.f;
#pragma unroll
    for (int l = 0; l < DL; ++l) {
        float e = __expf(sc[l] - m);
        sum += e;
        if (l == l0) el0 = e;
    }
    const float a = el0 / sum;

    // 5) multiply + evict-first stores
#pragma unroll
    for (int i = 0; i < 4; ++i) {
        v[i].x *= a; v[i].y *= a; v[i].z *= a; v[i].w *= a;
        __stcs(&q[i * 256 + t], v[i]);
    }
}

// ---------------------------------------------------------------------------
static inline void launch_pdl_g(const float* in, int b0) {
    cudaLaunchConfig_t cfg = {};
    cfg.gridDim = dim3(G_BLOCKS);
    cfg.blockDim = dim3(256);
    cfg.stream = 0;
    cudaLaunchAttribute attr[1];
    attr[0].id = cudaLaunchAttributeProgrammaticStreamSerialization;
    attr[0].val.programmaticStreamSerializationAllowed = 1;
    cfg.attrs = attr;
    cfg.numAttrs = 1;
    cudaLaunchKernelEx(&cfg, g_kernel, in, b0);
}

static inline void launch_pdl_m(const float* in, const float* Wm, float* out, int b0) {
    cudaLaunchConfig_t cfg = {};
    cfg.gridDim = dim3(M_BLOCKS);
    cfg.blockDim = dim3(256);
    cfg.stream = 0;
    cudaLaunchAttribute attr[1];
    attr[0].id = cudaLaunchAttributeProgrammaticStreamSerialization;
    attr[0].val.programmaticStreamSerializationAllowed = 1;
    cfg.attrs = attr;
    cfg.numAttrs = 1;
    cudaLaunchKernelEx(&cfg, m_kernel, in, Wm, out, b0);
}

extern "C" void kernel_launch(void* const* d_in, const int* in_sizes, int n_in,
                              void* d_out, int out_size) {
    const float* in = (const float*)d_in[0];   // [L,B,C,H,W]
    const float* Wm = (const float*)d_in[1];   // [C,C]
    float* out = (float*)d_out;

    g_kernel<<<G_BLOCKS, 256>>>(in, 0);        // G0 (plain launch)
    launch_pdl_m(in, Wm, out, 0);              // M0 (PDL on G0)
    launch_pdl_g(in, CHB);                     // G1 (PDL on M0; no data dep)
    launch_pdl_m(in, Wm, out, CHB);            // M1 (PDL on G1)
}